// round 12
// baseline (speedup 1.0000x reference)
#include <cuda_runtime.h>
#include <math.h>

#define TC   4096
#define TQ   128
#define DHID 356
#define DD2  712
#define NGT  1424
#define QACD 2848
#define UPB  8
#define NB   45      // ceil(356/8) blocks per direction

// ---------------- scratch (device globals; no allocation allowed) ----------------
__device__ float d_wt[5*100*100];
__device__ float d_x_ctx[TC*DHID];
__device__ float d_x_qry[TQ*DHID];
__device__ float d_t1[TC*DHID];
__device__ float d_t2[TC*DHID];
__device__ float d_xWf[TC*NGT];
__device__ float d_xWb[TC*NGT];
__device__ float d_Cb[TC*DD2];
__device__ float d_Qb[TQ*DD2];
__device__ float d_Qt[DD2*TQ];
__device__ float d_CW[TC*DD2];
__device__ float d_sim[TC*TQ];
__device__ float d_cw[TC];
__device__ float d_qw[TQ];
__device__ float d_rowmax[TC];
__device__ float d_alpha[TC];
__device__ float d_c2q[TC*DD2];
__device__ float d_q2c[DD2];
__device__ float d_qac[TC*QACD];
__device__ float d_Mb[TC*DD2];
__device__ float d_M2b[TC*DD2];
__device__ float d_lg[TC];
// Padded to one 128B line per block so pollers hit distinct LTS slices.
__device__ float g_hbuf[2][2][NB][32];   // [dir][parity][block][pad]
__device__ int   g_flags[2][NB][32];     // [dir][block][pad]

// ---------------- conv weight transpose: w[o][i][k] -> wt[k][i][o] ----------------
__global__ void k_convw(const float* __restrict__ w) {
    int idx = blockIdx.x*256 + threadIdx.x;
    if (idx < 50000) {
        int o = idx / 500; int r = idx - o*500; int i = r/5; int k = r - i*5;
        d_wt[(k*100+i)*100 + o] = w[idx];
    }
}

// ---------------- char CNN: one block per token ----------------
__global__ void k_charcnn(const int* __restrict__ chars, const float* __restrict__ emb,
                          const float* __restrict__ cb, float* __restrict__ xo)
{
    __shared__ float es[20][100];
    int t = blockIdx.x, tid = threadIdx.x;
    for (int idx = tid; idx < 2000; idx += 128) ((float*)es)[idx] = 0.f;
    __syncthreads();
    for (int idx = tid; idx < 1600; idx += 128) {
        int h = idx / 100, c = idx - h*100;
        es[h+2][c] = emb[chars[t*16+h]*100 + c];
    }
    __syncthreads();
    if (tid < 100) {
        float acc[16];
        float b = cb[tid];
        #pragma unroll
        for (int h = 0; h < 16; ++h) acc[h] = b;
        for (int i = 0; i < 100; ++i) {
            float ev[20];
            #pragma unroll
            for (int h2 = 0; h2 < 20; ++h2) ev[h2] = es[h2][i];
            #pragma unroll
            for (int k = 0; k < 5; ++k) {
                float wv = d_wt[(k*100+i)*100 + tid];
                #pragma unroll
                for (int h = 0; h < 16; ++h) acc[h] += ev[h+k]*wv;
            }
        }
        float m = acc[0];
        #pragma unroll
        for (int h = 1; h < 16; ++h) m = fmaxf(m, acc[h]);
        xo[t*DHID + tid] = m;
    }
}

// ---------------- elmo concat copy ----------------
__global__ void k_elmo(const float* __restrict__ e, float* __restrict__ xo, int T) {
    int idx = blockIdx.x*256 + threadIdx.x;
    if (idx < T*256) { int t = idx >> 8, j = idx & 255; xo[t*DHID + 100 + j] = e[idx]; }
}

// ---------------- SGEMM: C = A(MxK) * B(NxK)^T (+ bias[n]) ----------------
// 128x128 tile, BK=16, double-buffered smem, register prefetch, 1 sync/tile.
// (R7 proven version — untouched this round.)
__global__ __launch_bounds__(256)
void k_gemm_abt(const float* __restrict__ A, const float* __restrict__ B,
                const float* __restrict__ bias, float* __restrict__ C,
                int M, int N, int K)
{
    __shared__ float As[2][16][132];
    __shared__ float Bs[2][16][132];
    int bm = blockIdx.y*128, bn = blockIdx.x*128;
    int tid = threadIdx.x;
    int tx = tid & 15, ty = tid >> 4;
    int l0 = tid*2, l1 = tid*2 + 1;
    int r0 = l0 >> 2, c40 = (l0 & 3)*4;
    int r1 = l1 >> 2, c41 = (l1 & 3)*4;

    float4 pa0, pa1, pb0, pb1;

#define LOADV(dst, base, row, lim, kcol)                                              \
    dst = make_float4(0.f,0.f,0.f,0.f);                                               \
    if ((row) < (lim)) {                                                              \
        if ((kcol) + 3 < K) dst = *reinterpret_cast<const float4*>((base) + (size_t)(row)*K + (kcol)); \
        else if ((kcol) < K) {                                                        \
            const float* p_ = (base) + (size_t)(row)*K;                               \
            float t0_ = p_[(kcol)];                                                   \
            float t1_ = ((kcol)+1 < K) ? p_[(kcol)+1] : 0.f;                          \
            float t2_ = ((kcol)+2 < K) ? p_[(kcol)+2] : 0.f;                          \
            float t3_ = ((kcol)+3 < K) ? p_[(kcol)+3] : 0.f;                          \
            dst = make_float4(t0_, t1_, t2_, t3_);                                    \
        }                                                                             \
    }

#define LOADTILE(kt)                                \
    LOADV(pa0, A, bm + r0, M, (kt) + c40)           \
    LOADV(pa1, A, bm + r1, M, (kt) + c41)           \
    LOADV(pb0, B, bn + r0, N, (kt) + c40)           \
    LOADV(pb1, B, bn + r1, N, (kt) + c41)

#define STORETILE(buf)                                              \
    As[buf][c40+0][r0]=pa0.x; As[buf][c40+1][r0]=pa0.y;             \
    As[buf][c40+2][r0]=pa0.z; As[buf][c40+3][r0]=pa0.w;             \
    As[buf][c41+0][r1]=pa1.x; As[buf][c41+1][r1]=pa1.y;             \
    As[buf][c41+2][r1]=pa1.z; As[buf][c41+3][r1]=pa1.w;             \
    Bs[buf][c40+0][r0]=pb0.x; Bs[buf][c40+1][r0]=pb0.y;             \
    Bs[buf][c40+2][r0]=pb0.z; Bs[buf][c40+3][r0]=pb0.w;             \
    Bs[buf][c41+0][r1]=pb1.x; Bs[buf][c41+1][r1]=pb1.y;             \
    Bs[buf][c41+2][r1]=pb1.z; Bs[buf][c41+3][r1]=pb1.w;

    float acc[8][8];
    #pragma unroll
    for (int i = 0; i < 8; ++i)
        #pragma unroll
        for (int j = 0; j < 8; ++j) acc[i][j] = 0.f;

    LOADTILE(0)
    STORETILE(0)
    __syncthreads();
    int cur = 0;
    for (int kt = 0; kt < K; kt += 16) {
        bool hasNext = (kt + 16 < K);
        if (hasNext) { LOADTILE(kt+16) }
        #pragma unroll
        for (int k = 0; k < 16; ++k) {
            float4 a0 = *reinterpret_cast<const float4*>(&As[cur][k][ty*8]);
            float4 a1 = *reinterpret_cast<const float4*>(&As[cur][k][ty*8+4]);
            float4 b0 = *reinterpret_cast<const float4*>(&Bs[cur][k][tx*8]);
            float4 b1 = *reinterpret_cast<const float4*>(&Bs[cur][k][tx*8+4]);
            float a[8] = {a0.x,a0.y,a0.z,a0.w,a1.x,a1.y,a1.z,a1.w};
            float b[8] = {b0.x,b0.y,b0.z,b0.w,b1.x,b1.y,b1.z,b1.w};
            #pragma unroll
            for (int i = 0; i < 8; ++i)
                #pragma unroll
                for (int j = 0; j < 8; ++j) acc[i][j] += a[i]*b[j];
        }
        if (hasNext) {
            STORETILE(1-cur)      // other buffer; prev-iter sync protects it
            __syncthreads();
            cur ^= 1;
        }
    }
    #pragma unroll
    for (int i = 0; i < 8; ++i) {
        int row = bm + ty*8 + i;
        if (row >= M) continue;
        #pragma unroll
        for (int j = 0; j < 8; ++j) {
            int col = bn + tx*8 + j;
            if (col < N) {
                float v = acc[i][j];
                if (bias) v += bias[col];
                C[(size_t)row*N + col] = v;
            }
        }
    }
}

// ---------------- highway combine ----------------
__global__ void k_hwy(float* __restrict__ x, const float* __restrict__ g,
                      const float* __restrict__ p, int n)
{
    int i = blockIdx.x*256 + threadIdx.x;
    if (i < n) {
        float gv = 1.f/(1.f + expf(-g[i]));
        float pv = fmaxf(p[i], 0.f);
        x[i] = gv*pv + (1.f - gv)*x[i];
    }
}

// ---------------- flag reset before each scan ----------------
__global__ void k_zeroflags() {
    int n = 2*NB*32;
    for (int i = threadIdx.x; i < n; i += 1024) ((int*)g_flags)[i] = 0;
}

// ---------------- persistent BiLSTM scan: warp-specialized overlap, v2 ----------
// 45 blocks/direction, 8 units/block, 1024 threads.
// Producers = warps 0..15: warp p owns gate rows 2p, 2p+1 (16-lane halves;
//   ws rows padded to 368 floats so the two halves hit disjoint banks).
//   They write zred, join bar.sync(1,512); warp 0 then runs the R7 activation/
//   publish path with a SINGLE threadfence + flag store.
// Pollers = warps 16..31: ~3 foreign blocks each, hot spin from step start
//   (no nanosleep) — foreign-h L2 round trip overlaps our own gemv+publish.
//   Gather into hs[(t+1)&1] (parity double buffer). One syncthreads per step.
__global__ __launch_bounds__(1024, 1)
void k_scan(const float* __restrict__ xWf, const float* __restrict__ xWb,
            const float* __restrict__ Whh, const float* __restrict__ h0,
            float* __restrict__ out, int T)
{
    __shared__ float ws[32][368];
    __shared__ float hs[2][DHID];
    __shared__ float zred[32];
    __shared__ float cs[UPB];
    int dir = blockIdx.x / NB;
    int blk = blockIdx.x - dir*NB;
    int tid = threadIdx.x;
    int warp = tid >> 5, lane = tid & 31;
    const float* xW = dir ? xWb : xWf;
    const float* W  = Whh + (size_t)dir*NGT*DHID;
    int u0 = blk*UPB;

    // load this block's 32 Whh rows: row r = g*8+u
    for (int idx = tid; idx < 32*DHID; idx += 1024) {
        int rr = idx / DHID, k = idx - rr*DHID;
        int g2 = rr >> 3, u2 = rr & 7;
        ws[rr][k] = (u0+u2 < DHID) ? W[(size_t)(g2*DHID + u0 + u2)*DHID + k] : 0.f;
    }
    if (tid < DHID) hs[0][tid] = h0[dir*DHID + tid];
    if (tid < UPB)  cs[tid] = (u0+tid < DHID) ? h0[dir*DHID + u0 + tid] : 0.f;

    // producer state (warps 0..15): two gate rows per warp, 16-lane halves
    int half = lane >> 4, sub = lane & 15;
    int r = (warp << 1) | half;            // 0..31
    int gg = r >> 3;
    int uu_r = u0 + (r & 7);
    int grow = gg*DHID + uu_r;
    bool rowvalid = (warp < 16) && (uu_r < DHID);
    float xw = 0.f;
    if (rowvalid && sub == 0) {
        int ti0 = dir ? (T-1) : 0;
        xw = __ldg(&xW[(size_t)ti0*NGT + grow]);
    }
    // poller state (warps 16..31): 3 owned blocks each
    int pw = warp - 16;
    int pb0 = pw*3, pb1 = pw*3 + 1, pb2 = pw*3 + 2;
    __syncthreads();

    for (int t = 0; t < T; ++t) {
        if (warp < 16) {
            const float* hcur = hs[t & 1];
            float s0 = 0.f, s1 = 0.f;
            #pragma unroll
            for (int i = 0; i < 11; ++i) {
                int k = sub + (i << 5);
                s0 += ws[r][k]      * hcur[k];
                s1 += ws[r][k + 16] * hcur[k + 16];
            }
            if (sub < 4) s0 += ws[r][352 + sub] * hcur[352 + sub];
            float s = s0 + s1;
            // reduce within 16-lane half (xor keeps lanes inside the half)
            s += __shfl_xor_sync(0xffffffffu, s, 8);
            s += __shfl_xor_sync(0xffffffffu, s, 4);
            s += __shfl_xor_sync(0xffffffffu, s, 2);
            s += __shfl_xor_sync(0xffffffffu, s, 1);
            if (sub == 0) zred[r] = s + xw;
            asm volatile("bar.sync 1, 512;" ::: "memory");   // join 16 producer warps
            if (warp == 0) {
                float z = zred[lane];
                float a = ((lane >> 3) == 2) ? tanhf(z)
                                             : __fdividef(1.f, 1.f + __expf(-z));
                int u = lane & 7;
                float si = __shfl_sync(0xffffffffu, a, u);
                float sf = __shfl_sync(0xffffffffu, a, 8 + u);
                float tg = __shfl_sync(0xffffffffu, a, 16 + u);
                float so = __shfl_sync(0xffffffffu, a, 24 + u);
                int uu = u0 + lane;
                float h = 0.f;
                bool act = (lane < UPB) && (uu < DHID);
                if (act) {
                    float c = sf*cs[lane] + si*tg;
                    h = so*tanhf(c);
                    cs[lane] = c;
                    ((volatile float*)&g_hbuf[dir][t & 1][blk][0])[lane] = h;
                }
                __threadfence();                 // single fence per step
                __syncwarp(0xffffffffu);
                if (lane == 0)
                    *(volatile int*)&g_flags[dir][blk][0] = t + 1;   // release
                int ti = dir ? (T-1-t) : t;
                if (act) out[(size_t)ti*DD2 + dir*DHID + uu] = h;    // off crit path
            }
            // prefetch next step's xW
            if (rowvalid && sub == 0 && t + 1 < T) {
                int tn = dir ? (T-2-t) : (t+1);
                xw = __ldg(&xW[(size_t)tn*NGT + grow]);
            }
        } else {
            // pollers: hot spin from step start; gather each block on arrival
            int tgt = t + 1;
            float* hnext = hs[(t+1) & 1];
            bool n0 = (pb0 < NB), n1 = (pb1 < NB), n2 = (pb2 < NB);
            while (n0 || n1 || n2) {
                if (n0 && *(volatile int*)&g_flags[dir][pb0][0] >= tgt) {
                    int u = pb0*UPB + lane;
                    if (lane < UPB && u < DHID)
                        hnext[u] = ((volatile float*)&g_hbuf[dir][t & 1][pb0][0])[lane];
                    n0 = false;
                }
                if (n1 && *(volatile int*)&g_flags[dir][pb1][0] >= tgt) {
                    int u = pb1*UPB + lane;
                    if (lane < UPB && u < DHID)
                        hnext[u] = ((volatile float*)&g_hbuf[dir][t & 1][pb1][0])[lane];
                    n1 = false;
                }
                if (n2 && *(volatile int*)&g_flags[dir][pb2][0] >= tgt) {
                    int u = pb2*UPB + lane;
                    if (lane < UPB && u < DHID)
                        hnext[u] = ((volatile float*)&g_hbuf[dir][t & 1][pb2][0])[lane];
                    n2 = false;
                }
            }
        }
        __syncthreads();   // hs[(t+1)&1] complete for everyone
    }
}

// ---------------- row dot (gemv): o[t] = X[t,:K] . w ----------------
__global__ void k_rowdot(const float* __restrict__ X, const float* __restrict__ w,
                         float* __restrict__ o, int T, int K)
{
    int t = blockIdx.x*8 + (threadIdx.x >> 5);
    int lane = threadIdx.x & 31;
    if (t >= T) return;
    float s = 0.f;
    for (int k = lane; k < K; k += 32) s += X[(size_t)t*K + k]*w[k];
    #pragma unroll
    for (int off = 16; off; off >>= 1) s += __shfl_down_sync(0xffffffffu, s, off);
    if (lane == 0) o[t] = s;
}

__global__ void k_scalecols(const float* __restrict__ C, const float* __restrict__ w,
                            float* __restrict__ o, int n)
{
    int i = blockIdx.x*256 + threadIdx.x;
    if (i < n) o[i] = C[i]*w[i % DD2];
}

__global__ void k_qt() {
    int i = blockIdx.x*256 + threadIdx.x;
    if (i < DD2*TQ) { int j = i / TQ, q = i - j*TQ; d_Qt[i] = d_Qb[q*DD2 + j]; }
}

// sim[t][q] += cw[t]+qw[q]; rowmax; row softmax in-place
__global__ void k_simsm() {
    int t = blockIdx.x*8 + (threadIdx.x >> 5);
    int lane = threadIdx.x & 31;
    if (t >= TC) return;
    float cw = d_cw[t];
    float v[4];
    float m = -1e30f;
    #pragma unroll
    for (int i = 0; i < 4; ++i) {
        int q = lane + 32*i;
        v[i] = d_sim[t*TQ + q] + cw + d_qw[q];
        m = fmaxf(m, v[i]);
    }
    #pragma unroll
    for (int off = 16; off; off >>= 1) m = fmaxf(m, __shfl_xor_sync(0xffffffffu, m, off));
    float s = 0.f;
    #pragma unroll
    for (int i = 0; i < 4; ++i) { v[i] = expf(v[i]-m); s += v[i]; }
    #pragma unroll
    for (int off = 16; off; off >>= 1) s += __shfl_xor_sync(0xffffffffu, s, off);
    float inv = 1.f/s;
    #pragma unroll
    for (int i = 0; i < 4; ++i) d_sim[t*TQ + lane + 32*i] = v[i]*inv;
    if (lane == 0) d_rowmax[t] = m;
}

__device__ __forceinline__ float blkMax(float v, float* sh) {
    int lane = threadIdx.x & 31, w = threadIdx.x >> 5;
    #pragma unroll
    for (int o = 16; o; o >>= 1) v = fmaxf(v, __shfl_xor_sync(0xffffffffu, v, o));
    if (lane == 0) sh[w] = v;
    __syncthreads();
    if (w == 0) {
        float x = sh[lane];
        #pragma unroll
        for (int o = 16; o; o >>= 1) x = fmaxf(x, __shfl_xor_sync(0xffffffffu, x, o));
        if (lane == 0) sh[0] = x;
    }
    __syncthreads();
    float r = sh[0];
    __syncthreads();
    return r;
}
__device__ __forceinline__ float blkSum(float v, float* sh) {
    int lane = threadIdx.x & 31, w = threadIdx.x >> 5;
    #pragma unroll
    for (int o = 16; o; o >>= 1) v += __shfl_xor_sync(0xffffffffu, v, o);
    if (lane == 0) sh[w] = v;
    __syncthreads();
    if (w == 0) {
        float x = sh[lane];
        #pragma unroll
        for (int o = 16; o; o >>= 1) x += __shfl_xor_sync(0xffffffffu, x, o);
        if (lane == 0) sh[0] = x;
    }
    __syncthreads();
    float r = sh[0];
    __syncthreads();
    return r;
}

// softmax over rowmax (4096) -> alpha; also zero q2c
__global__ void k_alphasm() {
    __shared__ float sh[32];
    int tid = threadIdx.x;
    float m = -1e30f;
    for (int i = tid; i < TC; i += 1024) m = fmaxf(m, d_rowmax[i]);
    m = blkMax(m, sh);
    float s = 0.f;
    for (int i = tid; i < TC; i += 1024) s += expf(d_rowmax[i] - m);
    s = blkSum(s, sh);
    float inv = 1.f/s;
    for (int i = tid; i < TC; i += 1024) d_alpha[i] = expf(d_rowmax[i] - m)*inv;
    if (tid < DD2) d_q2c[tid] = 0.f;
}

__global__ void k_q2c() {
    int j = blockIdx.x*256 + threadIdx.x;
    int t0 = blockIdx.y*128;
    if (j >= DD2) return;
    float s = 0.f;
    for (int t = t0; t < t0+128; ++t) s += d_alpha[t]*d_Cb[(size_t)t*DD2 + j];
    atomicAdd(&d_q2c[j], s);
}

__global__ void k_qac() {
    int i = blockIdx.x*256 + threadIdx.x;
    if (i >= TC*DD2) return;
    int t = i / DD2, j = i - t*DD2;
    float c = d_Cb[i], a = d_c2q[i];
    float* row = d_qac + (size_t)t*QACD;
    row[j]        = c;
    row[DD2 + j]  = a;
    row[2*DD2 + j]= c*a;
    row[3*DD2 + j]= c*d_q2c[j];
}

// logits[t] = qac[t].w[0:2848] + M[t].w[2848:3560]
__global__ void k_logits(const float* __restrict__ Mx, const float* __restrict__ w) {
    int t = blockIdx.x*8 + (threadIdx.x >> 5);
    int lane = threadIdx.x & 31;
    if (t >= TC) return;
    float s = 0.f;
    const float* qr = d_qac + (size_t)t*QACD;
    for (int k = lane; k < QACD; k += 32) s += qr[k]*w[k];
    const float* mr = Mx + (size_t)t*DD2;
    for (int k = lane; k < DD2; k += 32) s += mr[k]*w[QACD + k];
    #pragma unroll
    for (int off = 16; off; off >>= 1) s += __shfl_down_sync(0xffffffffu, s, off);
    if (lane == 0) d_lg[t] = s;
}

__global__ void k_smout(float* __restrict__ o) {
    __shared__ float sh[32];
    int tid = threadIdx.x;
    float m = -1e30f;
    for (int i = tid; i < TC; i += 1024) m = fmaxf(m, d_lg[i]);
    m = blkMax(m, sh);
    float s = 0.f;
    for (int i = tid; i < TC; i += 1024) s += expf(d_lg[i] - m);
    s = blkSum(s, sh);
    float inv = 1.f/s;
    for (int i = tid; i < TC; i += 1024) o[i] = expf(d_lg[i] - m)*inv;
}

// ---------------- host ----------------
static float* symaddr(const void* sym) {
    void* p = nullptr;
    cudaGetSymbolAddress(&p, sym);
    return (float*)p;
}

static void gemm(const float* A, const float* B, const float* bias, float* C,
                 int M, int N, int K)
{
    dim3 grid((N + 127)/128, (M + 127)/128);
    k_gemm_abt<<<grid, 256>>>(A, B, bias, C, M, N, K);
}

static void scan(const float* xWf, const float* xWb, const float* Whh,
                 const float* h0, float* out, int T)
{
    k_zeroflags<<<1, 1024>>>();
    k_scan<<<2*NB, 1024>>>(xWf, xWb, Whh, h0, out, T);
}

extern "C" void kernel_launch(void* const* d_in, const int* in_sizes, int n_in,
                              void* d_out, int out_size)
{
    const int*   chars_ctx = (const int*)  d_in[0];
    const int*   chars_qry = (const int*)  d_in[1];
    const float* elmo_ctx  = (const float*)d_in[2];
    const float* elmo_qry  = (const float*)d_in[3];
    const float* char_emb  = (const float*)d_in[4];
    const float* conv_w    = (const float*)d_in[5];
    const float* conv_b    = (const float*)d_in[6];
    const float* hw_plain_w= (const float*)d_in[7];
    const float* hw_plain_b= (const float*)d_in[8];
    const float* hw_gate_w = (const float*)d_in[9];
    const float* hw_gate_b = (const float*)d_in[10];
    const float* ctx_Wih   = (const float*)d_in[11];
    const float* ctx_Whh   = (const float*)d_in[12];
    const float* ctx_b     = (const float*)d_in[13];
    const float* sim_w     = (const float*)d_in[14];
    const float* mod1_Wih  = (const float*)d_in[15];
    const float* mod1_Whh  = (const float*)d_in[16];
    const float* mod1_b    = (const float*)d_in[17];
    const float* mod2_Wih  = (const float*)d_in[18];
    const float* mod2_Whh  = (const float*)d_in[19];
    const float* mod2_b    = (const float*)d_in[20];
    const float* pos_Wih   = (const float*)d_in[21];
    const float* pos_Whh   = (const float*)d_in[22];
    const float* pos_b     = (const float*)d_in[23];
    const float* pos1_w    = (const float*)d_in[24];
    const float* pos2_w    = (const float*)d_in[25];
    const float* h0_ctx_c  = (const float*)d_in[26];
    const float* h0_ctx_q  = (const float*)d_in[27];
    const float* h0_mod    = (const float*)d_in[28];
    const float* h0_pos    = (const float*)d_in[29];
    float* out = (float*)d_out;

    float* x_ctx = symaddr(d_x_ctx);
    float* x_qry = symaddr(d_x_qry);
    float* t1    = symaddr(d_t1);
    float* t2    = symaddr(d_t2);
    float* xWf   = symaddr(d_xWf);
    float* xWb   = symaddr(d_xWb);
    float* Cb    = symaddr(d_Cb);
    float* Qb    = symaddr(d_Qb);
    float* Qt    = symaddr(d_Qt);
    float* CW    = symaddr(d_CW);
    float* sim   = symaddr(d_sim);
    float* cw    = symaddr(d_cw);
    float* qw    = symaddr(d_qw);
    float* c2q   = symaddr(d_c2q);
    float* qac   = symaddr(d_qac);
    float* Mb    = symaddr(d_Mb);
    float* M2b   = symaddr(d_M2b);

    // 1) char CNN + elmo concat
    k_convw<<<196, 256>>>(conv_w);
    k_charcnn<<<TC, 128>>>(chars_ctx, char_emb, conv_b, x_ctx);
    k_charcnn<<<TQ, 128>>>(chars_qry, char_emb, conv_b, x_qry);
    k_elmo<<<(TC*256 + 255)/256, 256>>>(elmo_ctx, x_ctx, TC);
    k_elmo<<<(TQ*256 + 255)/256, 256>>>(elmo_qry, x_qry, TQ);

    // 2) highway x2 (ctx and qry)
    for (int l = 0; l < 2; ++l) {
        gemm(x_ctx, hw_gate_w  + l*DHID*DHID, hw_gate_b  + l*DHID, t1, TC, DHID, DHID);
        gemm(x_ctx, hw_plain_w + l*DHID*DHID, hw_plain_b + l*DHID, t2, TC, DHID, DHID);
        k_hwy<<<(TC*DHID + 255)/256, 256>>>(x_ctx, t1, t2, TC*DHID);
        gemm(x_qry, hw_gate_w  + l*DHID*DHID, hw_gate_b  + l*DHID, t1, TQ, DHID, DHID);
        gemm(x_qry, hw_plain_w + l*DHID*DHID, hw_plain_b + l*DHID, t2, TQ, DHID, DHID);
        k_hwy<<<(TQ*DHID + 255)/256, 256>>>(x_qry, t1, t2, TQ*DHID);
    }

    // 3) context BiLSTM -> C
    gemm(x_ctx, ctx_Wih,             ctx_b,       xWf, TC, NGT, DHID);
    gemm(x_ctx, ctx_Wih + NGT*DHID,  ctx_b + NGT, xWb, TC, NGT, DHID);
    scan(xWf, xWb, ctx_Whh, h0_ctx_c, Cb, TC);

    // 4) query BiLSTM -> Q
    gemm(x_qry, ctx_Wih,             ctx_b,       xWf, TQ, NGT, DHID);
    gemm(x_qry, ctx_Wih + NGT*DHID,  ctx_b + NGT, xWb, TQ, NGT, DHID);
    scan(xWf, xWb, ctx_Whh, h0_ctx_q, Qb, TQ);

    // 5) attention
    k_rowdot<<<TC/8, 256>>>(Cb, sim_w,        cw, TC, DD2);
    k_rowdot<<<TQ/8, 256>>>(Qb, sim_w + DD2,  qw, TQ, DD2);
    k_scalecols<<<(TC*DD2 + 255)/256, 256>>>(Cb, sim_w + 2*DD2, CW, TC*DD2);
    gemm(CW, Qb, nullptr, sim, TC, TQ, DD2);      // (C*w_cq) @ Q^T
    k_simsm<<<TC/8, 256>>>();                     // + cw + qw, rowmax, softmax
    k_qt<<<(DD2*TQ + 255)/256, 256>>>();
    gemm(sim, Qt, nullptr, c2q, TC, DD2, TQ);     // attn @ Q
    k_alphasm<<<1, 1024>>>();
    { dim3 gq((DD2 + 255)/256, 32); k_q2c<<<gq, 256>>>(); }
    k_qac<<<(TC*DD2 + 255)/256, 256>>>();

    // 6) mod1 BiLSTM (input 2848) -> M
    gemm(qac, mod1_Wih,             mod1_b,       xWf, TC, NGT, QACD);
    gemm(qac, mod1_Wih + NGT*QACD,  mod1_b + NGT, xWb, TC, NGT, QACD);
    scan(xWf, xWb, mod1_Whh, h0_mod, Mb, TC);

    // 7) mod2 BiLSTM (input 712) -> M2
    gemm(Mb, mod2_Wih,            mod2_b,       xWf, TC, NGT, DD2);
    gemm(Mb, mod2_Wih + NGT*DD2,  mod2_b + NGT, xWb, TC, NGT, DD2);
    scan(xWf, xWb, mod2_Whh, h0_mod + 2*DHID, M2b, TC);

    // 8) pos1 = softmax([qac, M2] @ pos1_w)
    k_logits<<<TC/8, 256>>>(M2b, pos1_w);
    k_smout<<<1, 1024>>>(out);

    // 9) pos BiLSTM on M2 -> Mb (reuse), pos2
    gemm(M2b, pos_Wih,            pos_b,       xWf, TC, NGT, DD2);
    gemm(M2b, pos_Wih + NGT*DD2,  pos_b + NGT, xWb, TC, NGT, DD2);
    scan(xWf, xWb, pos_Whh, h0_pos, Mb, TC);
    k_logits<<<TC/8, 256>>>(Mb, pos2_w);
    k_smout<<<1, 1024>>>(out + TC);
}

// round 13
// speedup vs baseline: 1.8477x; 1.8477x over previous
#include <cuda_runtime.h>
#include <math.h>

#define TC   4096
#define TQ   128
#define DHID 356
#define DD2  712
#define NGT  1424
#define QACD 2848
#define UPB  6
#define NBLK 60      // ceil(356/6) blocks per direction

// ---------------- scratch (device globals; no allocation allowed) ----------------
__device__ float d_wt[5*100*100];
__device__ float d_x_ctx[TC*DHID];
__device__ float d_x_qry[TQ*DHID];
__device__ float d_t1[TC*DHID];
__device__ float d_t2[TC*DHID];
__device__ float d_xWf[TC*NGT];
__device__ float d_xWb[TC*NGT];
__device__ float d_Cb[TC*DD2];
__device__ float d_Qb[TQ*DD2];
__device__ float d_Qt[DD2*TQ];
__device__ float d_CW[TC*DD2];
__device__ float d_sim[TC*TQ];
__device__ float d_cw[TC];
__device__ float d_qw[TQ];
__device__ float d_rowmax[TC];
__device__ float d_alpha[TC];
__device__ float d_c2q[TC*DD2];
__device__ float d_q2c[DD2];
__device__ float d_qac[TC*QACD];
__device__ float d_Mb[TC*DD2];
__device__ float d_M2b[TC*DD2];
__device__ float d_lg[TC];
// One 128B line per (dir,parity,block): two 16B packets {tag,h0,h1,h2}{tag,h3,h4,h5}
__device__ float g_hline[2][2][NBLK][32];

__device__ __forceinline__ int4 ldv4(const int4* p) {
    int4 v;
    asm volatile("ld.volatile.global.v4.u32 {%0,%1,%2,%3}, [%4];"
        : "=r"(v.x), "=r"(v.y), "=r"(v.z), "=r"(v.w) : "l"(p));
    return v;
}
__device__ __forceinline__ void stv4(int4* p, int4 v) {
    asm volatile("st.volatile.global.v4.u32 [%0], {%1,%2,%3,%4};"
        :: "l"(p), "r"(v.x), "r"(v.y), "r"(v.z), "r"(v.w) : "memory");
}

// ---------------- conv weight transpose: w[o][i][k] -> wt[k][i][o] ----------------
__global__ void k_convw(const float* __restrict__ w) {
    int idx = blockIdx.x*256 + threadIdx.x;
    if (idx < 50000) {
        int o = idx / 500; int r = idx - o*500; int i = r/5; int k = r - i*5;
        d_wt[(k*100+i)*100 + o] = w[idx];
    }
}

// ---------------- char CNN: one block per token ----------------
__global__ void k_charcnn(const int* __restrict__ chars, const float* __restrict__ emb,
                          const float* __restrict__ cb, float* __restrict__ xo)
{
    __shared__ float es[20][100];
    int t = blockIdx.x, tid = threadIdx.x;
    for (int idx = tid; idx < 2000; idx += 128) ((float*)es)[idx] = 0.f;
    __syncthreads();
    for (int idx = tid; idx < 1600; idx += 128) {
        int h = idx / 100, c = idx - h*100;
        es[h+2][c] = emb[chars[t*16+h]*100 + c];
    }
    __syncthreads();
    if (tid < 100) {
        float acc[16];
        float b = cb[tid];
        #pragma unroll
        for (int h = 0; h < 16; ++h) acc[h] = b;
        for (int i = 0; i < 100; ++i) {
            float ev[20];
            #pragma unroll
            for (int h2 = 0; h2 < 20; ++h2) ev[h2] = es[h2][i];
            #pragma unroll
            for (int k = 0; k < 5; ++k) {
                float wv = d_wt[(k*100+i)*100 + tid];
                #pragma unroll
                for (int h = 0; h < 16; ++h) acc[h] += ev[h+k]*wv;
            }
        }
        float m = acc[0];
        #pragma unroll
        for (int h = 1; h < 16; ++h) m = fmaxf(m, acc[h]);
        xo[t*DHID + tid] = m;
    }
}

// ---------------- elmo concat copy ----------------
__global__ void k_elmo(const float* __restrict__ e, float* __restrict__ xo, int T) {
    int idx = blockIdx.x*256 + threadIdx.x;
    if (idx < T*256) { int t = idx >> 8, j = idx & 255; xo[t*DHID + 100 + j] = e[idx]; }
}

// ---------------- SGEMM: C = A(MxK) * B(NxK)^T (+ bias[n]) ----------------
// R7 proven version — untouched.
__global__ __launch_bounds__(256)
void k_gemm_abt(const float* __restrict__ A, const float* __restrict__ B,
                const float* __restrict__ bias, float* __restrict__ C,
                int M, int N, int K)
{
    __shared__ float As[2][16][132];
    __shared__ float Bs[2][16][132];
    int bm = blockIdx.y*128, bn = blockIdx.x*128;
    int tid = threadIdx.x;
    int tx = tid & 15, ty = tid >> 4;
    int l0 = tid*2, l1 = tid*2 + 1;
    int r0 = l0 >> 2, c40 = (l0 & 3)*4;
    int r1 = l1 >> 2, c41 = (l1 & 3)*4;

    float4 pa0, pa1, pb0, pb1;

#define LOADV(dst, base, row, lim, kcol)                                              \
    dst = make_float4(0.f,0.f,0.f,0.f);                                               \
    if ((row) < (lim)) {                                                              \
        if ((kcol) + 3 < K) dst = *reinterpret_cast<const float4*>((base) + (size_t)(row)*K + (kcol)); \
        else if ((kcol) < K) {                                                        \
            const float* p_ = (base) + (size_t)(row)*K;                               \
            float t0_ = p_[(kcol)];                                                   \
            float t1_ = ((kcol)+1 < K) ? p_[(kcol)+1] : 0.f;                          \
            float t2_ = ((kcol)+2 < K) ? p_[(kcol)+2] : 0.f;                          \
            float t3_ = ((kcol)+3 < K) ? p_[(kcol)+3] : 0.f;                          \
            dst = make_float4(t0_, t1_, t2_, t3_);                                    \
        }                                                                             \
    }

#define LOADTILE(kt)                                \
    LOADV(pa0, A, bm + r0, M, (kt) + c40)           \
    LOADV(pa1, A, bm + r1, M, (kt) + c41)           \
    LOADV(pb0, B, bn + r0, N, (kt) + c40)           \
    LOADV(pb1, B, bn + r1, N, (kt) + c41)

#define STORETILE(buf)                                              \
    As[buf][c40+0][r0]=pa0.x; As[buf][c40+1][r0]=pa0.y;             \
    As[buf][c40+2][r0]=pa0.z; As[buf][c40+3][r0]=pa0.w;             \
    As[buf][c41+0][r1]=pa1.x; As[buf][c41+1][r1]=pa1.y;             \
    As[buf][c41+2][r1]=pa1.z; As[buf][c41+3][r1]=pa1.w;             \
    Bs[buf][c40+0][r0]=pb0.x; Bs[buf][c40+1][r0]=pb0.y;             \
    Bs[buf][c40+2][r0]=pb0.z; Bs[buf][c40+3][r0]=pb0.w;             \
    Bs[buf][c41+0][r1]=pb1.x; Bs[buf][c41+1][r1]=pb1.y;             \
    Bs[buf][c41+2][r1]=pb1.z; Bs[buf][c41+3][r1]=pb1.w;

    float acc[8][8];
    #pragma unroll
    for (int i = 0; i < 8; ++i)
        #pragma unroll
        for (int j = 0; j < 8; ++j) acc[i][j] = 0.f;

    LOADTILE(0)
    STORETILE(0)
    __syncthreads();
    int cur = 0;
    for (int kt = 0; kt < K; kt += 16) {
        bool hasNext = (kt + 16 < K);
        if (hasNext) { LOADTILE(kt+16) }
        #pragma unroll
        for (int k = 0; k < 16; ++k) {
            float4 a0 = *reinterpret_cast<const float4*>(&As[cur][k][ty*8]);
            float4 a1 = *reinterpret_cast<const float4*>(&As[cur][k][ty*8+4]);
            float4 b0 = *reinterpret_cast<const float4*>(&Bs[cur][k][tx*8]);
            float4 b1 = *reinterpret_cast<const float4*>(&Bs[cur][k][tx*8+4]);
            float a[8] = {a0.x,a0.y,a0.z,a0.w,a1.x,a1.y,a1.z,a1.w};
            float b[8] = {b0.x,b0.y,b0.z,b0.w,b1.x,b1.y,b1.z,b1.w};
            #pragma unroll
            for (int i = 0; i < 8; ++i)
                #pragma unroll
                for (int j = 0; j < 8; ++j) acc[i][j] += a[i]*b[j];
        }
        if (hasNext) {
            STORETILE(1-cur)
            __syncthreads();
            cur ^= 1;
        }
    }
    #pragma unroll
    for (int i = 0; i < 8; ++i) {
        int row = bm + ty*8 + i;
        if (row >= M) continue;
        #pragma unroll
        for (int j = 0; j < 8; ++j) {
            int col = bn + tx*8 + j;
            if (col < N) {
                float v = acc[i][j];
                if (bias) v += bias[col];
                C[(size_t)row*N + col] = v;
            }
        }
    }
}

// ---------------- highway combine ----------------
__global__ void k_hwy(float* __restrict__ x, const float* __restrict__ g,
                      const float* __restrict__ p, int n)
{
    int i = blockIdx.x*256 + threadIdx.x;
    if (i < n) {
        float gv = 1.f/(1.f + expf(-g[i]));
        float pv = fmaxf(p[i], 0.f);
        x[i] = gv*pv + (1.f - gv)*x[i];
    }
}

// ---------------- line reset before each scan ----------------
__global__ void k_zerolines() {
    int n = 2*2*NBLK*32;
    for (int i = threadIdx.x; i < n; i += 1024) ((float*)g_hline)[i] = 0.f;
}

// ---------------- persistent BiLSTM scan: packed flag+data protocol ----------
// 60 blocks/direction, 6 units/block, 1024 threads.
// Warps 0..23: producers, 1 gate row each (24 rows = 4 gates x 6 units):
//   smem gemv (11 iters) -> reduce -> zred; bar.sync(1,768); warp 0 does
//   activations and publishes TWO 16B packets {tag=t+1, 3 h vals} each via a
//   single st.volatile.v4 — flag and data are one atomic L2 transaction:
//   no threadfence, no separate flag, ONE round trip for detection+data.
// Warps 24..31: pollers, 2 lanes per producer block (120 active lanes);
//   each lane spins on its packet and deposits 3 floats into hs[(t+1)&1].
// One __syncthreads per step.
__global__ __launch_bounds__(1024, 1)
void k_scan(const float* __restrict__ xWf, const float* __restrict__ xWb,
            const float* __restrict__ Whh, const float* __restrict__ h0,
            float* __restrict__ out, int T)
{
    __shared__ float ws[24][DHID];
    __shared__ float hs[2][NBLK*UPB + 4];
    __shared__ float zred[24];
    int dir = blockIdx.x / NBLK;
    int blk = blockIdx.x - dir*NBLK;
    int tid = threadIdx.x;
    int warp = tid >> 5, lane = tid & 31;
    const float* xW = dir ? xWb : xWf;
    const float* W  = Whh + (size_t)dir*NGT*DHID;
    int u0 = blk*UPB;

    // load this block's 24 Whh rows: row rr = g*6+u
    for (int idx = tid; idx < 24*DHID; idx += 1024) {
        int rr = idx / DHID, k = idx - rr*DHID;
        int g2 = rr / UPB, u2 = rr - g2*UPB;
        ws[rr][k] = (u0+u2 < DHID) ? W[(size_t)(g2*DHID + u0 + u2)*DHID + k] : 0.f;
    }
    if (tid < DHID) hs[0][tid] = h0[dir*DHID + tid];
    if (tid >= DHID && tid < NBLK*UPB + 4) hs[0][tid] = 0.f;
    if (tid < NBLK*UPB + 4) hs[1][tid] = 0.f;

    // producer row state (warps 0..23)
    int r  = warp;                       // gate row 0..23
    int gg = r / UPB, uq = r - gg*UPB;
    int uu_r = u0 + uq;
    int grow = gg*DHID + uu_r;
    bool rowvalid = (warp < 24) && (uu_r < DHID);
    float xw = 0.f;
    if (rowvalid && lane == 0) {
        int ti0 = dir ? (T-1) : 0;
        xw = __ldg(&xW[(size_t)ti0*NGT + grow]);
    }
    // warp0 cell state: lane u (<6) holds c for unit u0+u
    float creg = 0.f;
    if (warp == 0 && lane < UPB && u0 + lane < DHID)
        creg = h0[dir*DHID + u0 + lane];
    // poller state
    int pj = ((warp - 24) << 5) + lane;     // 0..255
    int pb = pj >> 1, phalf = pj & 1;
    bool pactive = (warp >= 24) && (pb < NBLK);
    const int4* psrc0 = (const int4*)&g_hline[dir][0][pactive ? pb : 0][phalf*4];
    const int4* psrc1 = (const int4*)&g_hline[dir][1][pactive ? pb : 0][phalf*4];
    __syncthreads();

    for (int t = 0; t < T; ++t) {
        if (warp < 24) {
            // gemv for this warp's gate row
            const float* hcur = hs[t & 1];
            float s = 0.f;
            #pragma unroll
            for (int i = 0; i < 11; ++i) s += ws[r][lane + 32*i]*hcur[lane + 32*i];
            if (lane < 4) s += ws[r][352 + lane]*hcur[352 + lane];
            #pragma unroll
            for (int o = 16; o; o >>= 1) s += __shfl_down_sync(0xffffffffu, s, o);
            if (lane == 0) zred[r] = s + xw;
            asm volatile("bar.sync 1, 768;" ::: "memory");   // join producers
            if (warp == 0) {
                float z = (lane < 24) ? zred[lane] : 0.f;
                float a = (lane >= 12 && lane < 18) ? tanhf(z)
                                                    : __fdividef(1.f, 1.f + __expf(-z));
                int u = (lane < UPB) ? lane : 0;
                float si = __shfl_sync(0xffffffffu, a, u);
                float sf = __shfl_sync(0xffffffffu, a, UPB + u);
                float tg = __shfl_sync(0xffffffffu, a, 2*UPB + u);
                float so = __shfl_sync(0xffffffffu, a, 3*UPB + u);
                float h = 0.f;
                int uu = u0 + lane;
                if (lane < UPB && uu < DHID) {
                    creg = sf*creg + si*tg;
                    h = so*tanhf(creg);
                }
                // pack two {tag, h, h, h} packets
                int srcb = 3*(lane & 1);
                float hA = __shfl_sync(0xffffffffu, h, srcb + 0);
                float hB = __shfl_sync(0xffffffffu, h, srcb + 1);
                float hC = __shfl_sync(0xffffffffu, h, srcb + 2);
                if (lane < 2) {
                    int4 v;
                    v.x = t + 1;
                    v.y = __float_as_int(hA);
                    v.z = __float_as_int(hB);
                    v.w = __float_as_int(hC);
                    stv4((int4*)&g_hline[dir][t & 1][blk][lane*4], v);
                }
                int ti = dir ? (T-1-t) : t;
                if (lane < UPB && uu < DHID)
                    out[(size_t)ti*DD2 + dir*DHID + uu] = h;    // off crit path
            }
            // prefetch next step's xW
            if (rowvalid && lane == 0 && t + 1 < T) {
                int tn = dir ? (T-2-t) : (t+1);
                xw = __ldg(&xW[(size_t)tn*NGT + grow]);
            }
        } else {
            // pollers: single-RTT detect+gather
            int tag = t + 1;
            float* hn = hs[(t+1) & 1];
            const int4* src = (t & 1) ? psrc1 : psrc0;
            bool done = !pactive;
            while (__any_sync(0xffffffffu, !done)) {
                if (!done) {
                    int4 v = ldv4(src);
                    if (v.x == tag) {
                        int u = pb*UPB + phalf*3;
                        hn[u]   = __int_as_float(v.y);
                        hn[u+1] = __int_as_float(v.z);
                        hn[u+2] = __int_as_float(v.w);
                        done = true;
                    }
                }
            }
        }
        __syncthreads();   // hs[(t+1)&1] complete for everyone
    }
}

// ---------------- row dot (gemv): o[t] = X[t,:K] . w ----------------
__global__ void k_rowdot(const float* __restrict__ X, const float* __restrict__ w,
                         float* __restrict__ o, int T, int K)
{
    int t = blockIdx.x*8 + (threadIdx.x >> 5);
    int lane = threadIdx.x & 31;
    if (t >= T) return;
    float s = 0.f;
    for (int k = lane; k < K; k += 32) s += X[(size_t)t*K + k]*w[k];
    #pragma unroll
    for (int off = 16; off; off >>= 1) s += __shfl_down_sync(0xffffffffu, s, off);
    if (lane == 0) o[t] = s;
}

__global__ void k_scalecols(const float* __restrict__ C, const float* __restrict__ w,
                            float* __restrict__ o, int n)
{
    int i = blockIdx.x*256 + threadIdx.x;
    if (i < n) o[i] = C[i]*w[i % DD2];
}

__global__ void k_qt() {
    int i = blockIdx.x*256 + threadIdx.x;
    if (i < DD2*TQ) { int j = i / TQ, q = i - j*TQ; d_Qt[i] = d_Qb[q*DD2 + j]; }
}

// sim[t][q] += cw[t]+qw[q]; rowmax; row softmax in-place
__global__ void k_simsm() {
    int t = blockIdx.x*8 + (threadIdx.x >> 5);
    int lane = threadIdx.x & 31;
    if (t >= TC) return;
    float cw = d_cw[t];
    float v[4];
    float m = -1e30f;
    #pragma unroll
    for (int i = 0; i < 4; ++i) {
        int q = lane + 32*i;
        v[i] = d_sim[t*TQ + q] + cw + d_qw[q];
        m = fmaxf(m, v[i]);
    }
    #pragma unroll
    for (int off = 16; off; off >>= 1) m = fmaxf(m, __shfl_xor_sync(0xffffffffu, m, off));
    float s = 0.f;
    #pragma unroll
    for (int i = 0; i < 4; ++i) { v[i] = expf(v[i]-m); s += v[i]; }
    #pragma unroll
    for (int off = 16; off; off >>= 1) s += __shfl_xor_sync(0xffffffffu, s, off);
    float inv = 1.f/s;
    #pragma unroll
    for (int i = 0; i < 4; ++i) d_sim[t*TQ + lane + 32*i] = v[i]*inv;
    if (lane == 0) d_rowmax[t] = m;
}

__device__ __forceinline__ float blkMax(float v, float* sh) {
    int lane = threadIdx.x & 31, w = threadIdx.x >> 5;
    #pragma unroll
    for (int o = 16; o; o >>= 1) v = fmaxf(v, __shfl_xor_sync(0xffffffffu, v, o));
    if (lane == 0) sh[w] = v;
    __syncthreads();
    if (w == 0) {
        float x = sh[lane];
        #pragma unroll
        for (int o = 16; o; o >>= 1) x = fmaxf(x, __shfl_xor_sync(0xffffffffu, x, o));
        if (lane == 0) sh[0] = x;
    }
    __syncthreads();
    float r = sh[0];
    __syncthreads();
    return r;
}
__device__ __forceinline__ float blkSum(float v, float* sh) {
    int lane = threadIdx.x & 31, w = threadIdx.x >> 5;
    #pragma unroll
    for (int o = 16; o; o >>= 1) v += __shfl_xor_sync(0xffffffffu, v, o);
    if (lane == 0) sh[w] = v;
    __syncthreads();
    if (w == 0) {
        float x = sh[lane];
        #pragma unroll
        for (int o = 16; o; o >>= 1) x += __shfl_xor_sync(0xffffffffu, x, o);
        if (lane == 0) sh[0] = x;
    }
    __syncthreads();
    float r = sh[0];
    __syncthreads();
    return r;
}

// softmax over rowmax (4096) -> alpha; also zero q2c
__global__ void k_alphasm() {
    __shared__ float sh[32];
    int tid = threadIdx.x;
    float m = -1e30f;
    for (int i = tid; i < TC; i += 1024) m = fmaxf(m, d_rowmax[i]);
    m = blkMax(m, sh);
    float s = 0.f;
    for (int i = tid; i < TC; i += 1024) s += expf(d_rowmax[i] - m);
    s = blkSum(s, sh);
    float inv = 1.f/s;
    for (int i = tid; i < TC; i += 1024) d_alpha[i] = expf(d_rowmax[i] - m)*inv;
    if (tid < DD2) d_q2c[tid] = 0.f;
}

__global__ void k_q2c() {
    int j = blockIdx.x*256 + threadIdx.x;
    int t0 = blockIdx.y*128;
    if (j >= DD2) return;
    float s = 0.f;
    for (int t = t0; t < t0+128; ++t) s += d_alpha[t]*d_Cb[(size_t)t*DD2 + j];
    atomicAdd(&d_q2c[j], s);
}

__global__ void k_qac() {
    int i = blockIdx.x*256 + threadIdx.x;
    if (i >= TC*DD2) return;
    int t = i / DD2, j = i - t*DD2;
    float c = d_Cb[i], a = d_c2q[i];
    float* row = d_qac + (size_t)t*QACD;
    row[j]        = c;
    row[DD2 + j]  = a;
    row[2*DD2 + j]= c*a;
    row[3*DD2 + j]= c*d_q2c[j];
}

// logits[t] = qac[t].w[0:2848] + M[t].w[2848:3560]
__global__ void k_logits(const float* __restrict__ Mx, const float* __restrict__ w) {
    int t = blockIdx.x*8 + (threadIdx.x >> 5);
    int lane = threadIdx.x & 31;
    if (t >= TC) return;
    float s = 0.f;
    const float* qr = d_qac + (size_t)t*QACD;
    for (int k = lane; k < QACD; k += 32) s += qr[k]*w[k];
    const float* mr = Mx + (size_t)t*DD2;
    for (int k = lane; k < DD2; k += 32) s += mr[k]*w[QACD + k];
    #pragma unroll
    for (int off = 16; off; off >>= 1) s += __shfl_down_sync(0xffffffffu, s, off);
    if (lane == 0) d_lg[t] = s;
}

__global__ void k_smout(float* __restrict__ o) {
    __shared__ float sh[32];
    int tid = threadIdx.x;
    float m = -1e30f;
    for (int i = tid; i < TC; i += 1024) m = fmaxf(m, d_lg[i]);
    m = blkMax(m, sh);
    float s = 0.f;
    for (int i = tid; i < TC; i += 1024) s += expf(d_lg[i] - m);
    s = blkSum(s, sh);
    float inv = 1.f/s;
    for (int i = tid; i < TC; i += 1024) o[i] = expf(d_lg[i] - m)*inv;
}

// ---------------- host ----------------
static float* symaddr(const void* sym) {
    void* p = nullptr;
    cudaGetSymbolAddress(&p, sym);
    return (float*)p;
}

static void gemm(const float* A, const float* B, const float* bias, float* C,
                 int M, int N, int K)
{
    dim3 grid((N + 127)/128, (M + 127)/128);
    k_gemm_abt<<<grid, 256>>>(A, B, bias, C, M, N, K);
}

static void scan(const float* xWf, const float* xWb, const float* Whh,
                 const float* h0, float* out, int T)
{
    k_zerolines<<<1, 1024>>>();
    k_scan<<<2*NBLK, 1024>>>(xWf, xWb, Whh, h0, out, T);
}

extern "C" void kernel_launch(void* const* d_in, const int* in_sizes, int n_in,
                              void* d_out, int out_size)
{
    const int*   chars_ctx = (const int*)  d_in[0];
    const int*   chars_qry = (const int*)  d_in[1];
    const float* elmo_ctx  = (const float*)d_in[2];
    const float* elmo_qry  = (const float*)d_in[3];
    const float* char_emb  = (const float*)d_in[4];
    const float* conv_w    = (const float*)d_in[5];
    const float* conv_b    = (const float*)d_in[6];
    const float* hw_plain_w= (const float*)d_in[7];
    const float* hw_plain_b= (const float*)d_in[8];
    const float* hw_gate_w = (const float*)d_in[9];
    const float* hw_gate_b = (const float*)d_in[10];
    const float* ctx_Wih   = (const float*)d_in[11];
    const float* ctx_Whh   = (const float*)d_in[12];
    const float* ctx_b     = (const float*)d_in[13];
    const float* sim_w     = (const float*)d_in[14];
    const float* mod1_Wih  = (const float*)d_in[15];
    const float* mod1_Whh  = (const float*)d_in[16];
    const float* mod1_b    = (const float*)d_in[17];
    const float* mod2_Wih  = (const float*)d_in[18];
    const float* mod2_Whh  = (const float*)d_in[19];
    const float* mod2_b    = (const float*)d_in[20];
    const float* pos_Wih   = (const float*)d_in[21];
    const float* pos_Whh   = (const float*)d_in[22];
    const float* pos_b     = (const float*)d_in[23];
    const float* pos1_w    = (const float*)d_in[24];
    const float* pos2_w    = (const float*)d_in[25];
    const float* h0_ctx_c  = (const float*)d_in[26];
    const float* h0_ctx_q  = (const float*)d_in[27];
    const float* h0_mod    = (const float*)d_in[28];
    const float* h0_pos    = (const float*)d_in[29];
    float* out = (float*)d_out;

    float* x_ctx = symaddr(d_x_ctx);
    float* x_qry = symaddr(d_x_qry);
    float* t1    = symaddr(d_t1);
    float* t2    = symaddr(d_t2);
    float* xWf   = symaddr(d_xWf);
    float* xWb   = symaddr(d_xWb);
    float* Cb    = symaddr(d_Cb);
    float* Qb    = symaddr(d_Qb);
    float* Qt    = symaddr(d_Qt);
    float* CW    = symaddr(d_CW);
    float* sim   = symaddr(d_sim);
    float* cw    = symaddr(d_cw);
    float* qw    = symaddr(d_qw);
    float* c2q   = symaddr(d_c2q);
    float* qac   = symaddr(d_qac);
    float* Mb    = symaddr(d_Mb);
    float* M2b   = symaddr(d_M2b);

    // 1) char CNN + elmo concat
    k_convw<<<196, 256>>>(conv_w);
    k_charcnn<<<TC, 128>>>(chars_ctx, char_emb, conv_b, x_ctx);
    k_charcnn<<<TQ, 128>>>(chars_qry, char_emb, conv_b, x_qry);
    k_elmo<<<(TC*256 + 255)/256, 256>>>(elmo_ctx, x_ctx, TC);
    k_elmo<<<(TQ*256 + 255)/256, 256>>>(elmo_qry, x_qry, TQ);

    // 2) highway x2 (ctx and qry)
    for (int l = 0; l < 2; ++l) {
        gemm(x_ctx, hw_gate_w  + l*DHID*DHID, hw_gate_b  + l*DHID, t1, TC, DHID, DHID);
        gemm(x_ctx, hw_plain_w + l*DHID*DHID, hw_plain_b + l*DHID, t2, TC, DHID, DHID);
        k_hwy<<<(TC*DHID + 255)/256, 256>>>(x_ctx, t1, t2, TC*DHID);
        gemm(x_qry, hw_gate_w  + l*DHID*DHID, hw_gate_b  + l*DHID, t1, TQ, DHID, DHID);
        gemm(x_qry, hw_plain_w + l*DHID*DHID, hw_plain_b + l*DHID, t2, TQ, DHID, DHID);
        k_hwy<<<(TQ*DHID + 255)/256, 256>>>(x_qry, t1, t2, TQ*DHID);
    }

    // 3) context BiLSTM -> C
    gemm(x_ctx, ctx_Wih,             ctx_b,       xWf, TC, NGT, DHID);
    gemm(x_ctx, ctx_Wih + NGT*DHID,  ctx_b + NGT, xWb, TC, NGT, DHID);
    scan(xWf, xWb, ctx_Whh, h0_ctx_c, Cb, TC);

    // 4) query BiLSTM -> Q
    gemm(x_qry, ctx_Wih,             ctx_b,       xWf, TQ, NGT, DHID);
    gemm(x_qry, ctx_Wih + NGT*DHID,  ctx_b + NGT, xWb, TQ, NGT, DHID);
    scan(xWf, xWb, ctx_Whh, h0_ctx_q, Qb, TQ);

    // 5) attention
    k_rowdot<<<TC/8, 256>>>(Cb, sim_w,        cw, TC, DD2);
    k_rowdot<<<TQ/8, 256>>>(Qb, sim_w + DD2,  qw, TQ, DD2);
    k_scalecols<<<(TC*DD2 + 255)/256, 256>>>(Cb, sim_w + 2*DD2, CW, TC*DD2);
    gemm(CW, Qb, nullptr, sim, TC, TQ, DD2);      // (C*w_cq) @ Q^T
    k_simsm<<<TC/8, 256>>>();                     // + cw + qw, rowmax, softmax
    k_qt<<<(DD2*TQ + 255)/256, 256>>>();
    gemm(sim, Qt, nullptr, c2q, TC, DD2, TQ);     // attn @ Q
    k_alphasm<<<1, 1024>>>();
    { dim3 gq((DD2 + 255)/256, 32); k_q2c<<<gq, 256>>>(); }
    k_qac<<<(TC*DD2 + 255)/256, 256>>>();

    // 6) mod1 BiLSTM (input 2848) -> M
    gemm(qac, mod1_Wih,             mod1_b,       xWf, TC, NGT, QACD);
    gemm(qac, mod1_Wih + NGT*QACD,  mod1_b + NGT, xWb, TC, NGT, QACD);
    scan(xWf, xWb, mod1_Whh, h0_mod, Mb, TC);

    // 7) mod2 BiLSTM (input 712) -> M2
    gemm(Mb, mod2_Wih,            mod2_b,       xWf, TC, NGT, DD2);
    gemm(Mb, mod2_Wih + NGT*DD2,  mod2_b + NGT, xWb, TC, NGT, DD2);
    scan(xWf, xWb, mod2_Whh, h0_mod + 2*DHID, M2b, TC);

    // 8) pos1 = softmax([qac, M2] @ pos1_w)
    k_logits<<<TC/8, 256>>>(M2b, pos1_w);
    k_smout<<<1, 1024>>>(out);

    // 9) pos BiLSTM on M2 -> Mb (reuse), pos2
    gemm(M2b, pos_Wih,            pos_b,       xWf, TC, NGT, DD2);
    gemm(M2b, pos_Wih + NGT*DD2,  pos_b + NGT, xWb, TC, NGT, DD2);
    scan(xWf, xWb, pos_Whh, h0_pos, Mb, TC);
    k_logits<<<TC/8, 256>>>(Mb, pos2_w);
    k_smout<<<1, 1024>>>(out + TC);
}

// round 15
// speedup vs baseline: 1.8618x; 1.0076x over previous
#include <cuda_runtime.h>
#include <math.h>

#define TC   4096
#define TQ   128
#define DHID 356
#define DD2  712
#define NGT  1424
#define QACD 2848
#define UPB  6
#define NBLK 60      // ceil(356/6) blocks per direction

// ---------------- scratch (device globals; no allocation allowed) ----------------
__device__ float d_wt[5*100*100];
__device__ float d_x_ctx[TC*DHID];
__device__ float d_x_qry[TQ*DHID];
__device__ float d_t1[TC*DHID];
__device__ float d_t2[TC*DHID];
__device__ float d_xW[TC*2*NGT];        // combined fwd|bwd gate pre-activations
__device__ float d_Cb[TC*DD2];
__device__ float d_Qb[TQ*DD2];
__device__ float d_Qt[DD2*TQ];
__device__ float d_CW[TC*DD2];
__device__ float d_sim[TC*TQ];
__device__ float d_cw[TC];
__device__ float d_qw[TQ];
__device__ float d_rowmax[TC];
__device__ float d_alpha[TC];
__device__ float d_c2q[TC*DD2];
__device__ float d_q2c[DD2];
__device__ float d_qac[TC*QACD];
__device__ float d_Mb[TC*DD2];
__device__ float d_M2b[TC*DD2];
__device__ float d_lg[TC];
// One 128B line per (dir,parity,block): two 16B packets {tag,h0,h1,h2}{tag,h3,h4,h5}
__device__ float g_hline[2][2][NBLK][32];

__device__ __forceinline__ int4 ldv4(const int4* p) {
    int4 v;
    asm volatile("ld.volatile.global.v4.u32 {%0,%1,%2,%3}, [%4];"
        : "=r"(v.x), "=r"(v.y), "=r"(v.z), "=r"(v.w) : "l"(p));
    return v;
}
__device__ __forceinline__ void stv4(int4* p, int4 v) {
    asm volatile("st.volatile.global.v4.u32 [%0], {%1,%2,%3,%4};"
        :: "l"(p), "r"(v.x), "r"(v.y), "r"(v.z), "r"(v.w) : "memory");
}

// ---------------- conv weight transpose: w[o][i][k] -> wt[k][i][o] ----------------
__global__ void k_convw(const float* __restrict__ w) {
    int idx = blockIdx.x*256 + threadIdx.x;
    if (idx < 50000) {
        int o = idx / 500; int r = idx - o*500; int i = r/5; int k = r - i*5;
        d_wt[(k*100+i)*100 + o] = w[idx];
    }
}

// ---------------- char CNN: one block per token ----------------
__global__ void k_charcnn(const int* __restrict__ chars, const float* __restrict__ emb,
                          const float* __restrict__ cb, float* __restrict__ xo)
{
    __shared__ float es[20][100];
    int t = blockIdx.x, tid = threadIdx.x;
    for (int idx = tid; idx < 2000; idx += 128) ((float*)es)[idx] = 0.f;
    __syncthreads();
    for (int idx = tid; idx < 1600; idx += 128) {
        int h = idx / 100, c = idx - h*100;
        es[h+2][c] = emb[chars[t*16+h]*100 + c];
    }
    __syncthreads();
    if (tid < 100) {
        float acc[16];
        float b = cb[tid];
        #pragma unroll
        for (int h = 0; h < 16; ++h) acc[h] = b;
        for (int i = 0; i < 100; ++i) {
            float ev[20];
            #pragma unroll
            for (int h2 = 0; h2 < 20; ++h2) ev[h2] = es[h2][i];
            #pragma unroll
            for (int k = 0; k < 5; ++k) {
                float wv = d_wt[(k*100+i)*100 + tid];
                #pragma unroll
                for (int h = 0; h < 16; ++h) acc[h] += ev[h+k]*wv;
            }
        }
        float m = acc[0];
        #pragma unroll
        for (int h = 1; h < 16; ++h) m = fmaxf(m, acc[h]);
        xo[t*DHID + tid] = m;
    }
}

// ---------------- elmo concat copy ----------------
__global__ void k_elmo(const float* __restrict__ e, float* __restrict__ xo, int T) {
    int idx = blockIdx.x*256 + threadIdx.x;
    if (idx < T*256) { int t = idx >> 8, j = idx & 255; xo[t*DHID + 100 + j] = e[idx]; }
}

// ---------------- SGEMM v2: C = A(MxK) * B(NxK)^T (+ bias[n]) ----------------
// 64x128 tile, 128 threads, 8x8 microtile, BK=16 double-buffered.
// As inner pad = 68 floats (272B = 16*17) so float4 LDS reads stay 16B-aligned
// for every k (66 floats = 264B caused the R14 misaligned-address trap).
__global__ __launch_bounds__(128)
void k_gemm_abt(const float* __restrict__ A, const float* __restrict__ B,
                const float* __restrict__ bias, float* __restrict__ C,
                int M, int N, int K)
{
    __shared__ float As[2][16][68];
    __shared__ float Bs[2][16][132];
    int bm = blockIdx.y*64, bn = blockIdx.x*128;
    int tid = threadIdx.x;
    int tx = tid & 15, ty = tid >> 4;

    int arow = tid >> 1;              // 0..63
    int akk  = (tid & 1)*8;           // 0 or 8
    int brow = tid;                   // 0..127

    float4 pa0, pa1, pb0, pb1, pb2, pb3;

#define LOADV(dst, base, row, lim, kcol)                                              \
    dst = make_float4(0.f,0.f,0.f,0.f);                                               \
    if ((row) < (lim)) {                                                              \
        if ((kcol) + 3 < K) dst = *reinterpret_cast<const float4*>((base) + (size_t)(row)*K + (kcol)); \
        else if ((kcol) < K) {                                                        \
            const float* p_ = (base) + (size_t)(row)*K;                               \
            float t0_ = p_[(kcol)];                                                   \
            float t1_ = ((kcol)+1 < K) ? p_[(kcol)+1] : 0.f;                          \
            float t2_ = ((kcol)+2 < K) ? p_[(kcol)+2] : 0.f;                          \
            float t3_ = ((kcol)+3 < K) ? p_[(kcol)+3] : 0.f;                          \
            dst = make_float4(t0_, t1_, t2_, t3_);                                    \
        }                                                                             \
    }

#define LOADTILE(kt)                                  \
    LOADV(pa0, A, bm + arow, M, (kt) + akk)           \
    LOADV(pa1, A, bm + arow, M, (kt) + akk + 4)       \
    LOADV(pb0, B, bn + brow, N, (kt) + 0)             \
    LOADV(pb1, B, bn + brow, N, (kt) + 4)             \
    LOADV(pb2, B, bn + brow, N, (kt) + 8)             \
    LOADV(pb3, B, bn + brow, N, (kt) + 12)

#define STORETILE(buf)                                                  \
    As[buf][akk+0][arow]=pa0.x; As[buf][akk+1][arow]=pa0.y;             \
    As[buf][akk+2][arow]=pa0.z; As[buf][akk+3][arow]=pa0.w;             \
    As[buf][akk+4][arow]=pa1.x; As[buf][akk+5][arow]=pa1.y;             \
    As[buf][akk+6][arow]=pa1.z; As[buf][akk+7][arow]=pa1.w;             \
    Bs[buf][0][brow]=pb0.x;  Bs[buf][1][brow]=pb0.y;                    \
    Bs[buf][2][brow]=pb0.z;  Bs[buf][3][brow]=pb0.w;                    \
    Bs[buf][4][brow]=pb1.x;  Bs[buf][5][brow]=pb1.y;                    \
    Bs[buf][6][brow]=pb1.z;  Bs[buf][7][brow]=pb1.w;                    \
    Bs[buf][8][brow]=pb2.x;  Bs[buf][9][brow]=pb2.y;                    \
    Bs[buf][10][brow]=pb2.z; Bs[buf][11][brow]=pb2.w;                   \
    Bs[buf][12][brow]=pb3.x; Bs[buf][13][brow]=pb3.y;                   \
    Bs[buf][14][brow]=pb3.z; Bs[buf][15][brow]=pb3.w;

    float acc[8][8];
    #pragma unroll
    for (int i = 0; i < 8; ++i)
        #pragma unroll
        for (int j = 0; j < 8; ++j) acc[i][j] = 0.f;

    LOADTILE(0)
    STORETILE(0)
    __syncthreads();
    int cur = 0;
    for (int kt = 0; kt < K; kt += 16) {
        bool hasNext = (kt + 16 < K);
        if (hasNext) { LOADTILE(kt+16) }
        #pragma unroll
        for (int k = 0; k < 16; ++k) {
            float4 a0 = *reinterpret_cast<const float4*>(&As[cur][k][ty*8]);
            float4 a1 = *reinterpret_cast<const float4*>(&As[cur][k][ty*8+4]);
            float4 b0 = *reinterpret_cast<const float4*>(&Bs[cur][k][tx*8]);
            float4 b1 = *reinterpret_cast<const float4*>(&Bs[cur][k][tx*8+4]);
            float a[8] = {a0.x,a0.y,a0.z,a0.w,a1.x,a1.y,a1.z,a1.w};
            float b[8] = {b0.x,b0.y,b0.z,b0.w,b1.x,b1.y,b1.z,b1.w};
            #pragma unroll
            for (int i = 0; i < 8; ++i)
                #pragma unroll
                for (int j = 0; j < 8; ++j) acc[i][j] += a[i]*b[j];
        }
        if (hasNext) {
            STORETILE(1-cur)
            __syncthreads();
            cur ^= 1;
        }
    }
    #pragma unroll
    for (int i = 0; i < 8; ++i) {
        int row = bm + ty*8 + i;
        if (row >= M) continue;
        #pragma unroll
        for (int j = 0; j < 8; ++j) {
            int col = bn + tx*8 + j;
            if (col < N) {
                float v = acc[i][j];
                if (bias) v += bias[col];
                C[(size_t)row*N + col] = v;
            }
        }
    }
}

// ---------------- highway combine ----------------
__global__ void k_hwy(float* __restrict__ x, const float* __restrict__ g,
                      const float* __restrict__ p, int n)
{
    int i = blockIdx.x*256 + threadIdx.x;
    if (i < n) {
        float gv = 1.f/(1.f + expf(-g[i]));
        float pv = fmaxf(p[i], 0.f);
        x[i] = gv*pv + (1.f - gv)*x[i];
    }
}

// ---------------- line reset before each scan ----------------
__global__ void k_zerolines() {
    int n = 2*2*NBLK*32;
    for (int i = threadIdx.x; i < n; i += 1024) ((float*)g_hline)[i] = 0.f;
}

// ---------------- persistent BiLSTM scan: packed flag+data (R13 proven) ----------
// xW is the COMBINED (T, 2848) buffer: row stride 2*NGT, fwd at col 0, bwd at NGT.
__global__ __launch_bounds__(1024, 1)
void k_scan(const float* __restrict__ xW,
            const float* __restrict__ Whh, const float* __restrict__ h0,
            float* __restrict__ out, int T)
{
    __shared__ float ws[24][DHID];
    __shared__ float hs[2][NBLK*UPB + 4];
    __shared__ float zred[24];
    int dir = blockIdx.x / NBLK;
    int blk = blockIdx.x - dir*NBLK;
    int tid = threadIdx.x;
    int warp = tid >> 5, lane = tid & 31;
    const float* W  = Whh + (size_t)dir*NGT*DHID;
    int u0 = blk*UPB;
    const int XS = 2*NGT;

    for (int idx = tid; idx < 24*DHID; idx += 1024) {
        int rr = idx / DHID, k = idx - rr*DHID;
        int g2 = rr / UPB, u2 = rr - g2*UPB;
        ws[rr][k] = (u0+u2 < DHID) ? W[(size_t)(g2*DHID + u0 + u2)*DHID + k] : 0.f;
    }
    if (tid < DHID) hs[0][tid] = h0[dir*DHID + tid];
    if (tid >= DHID && tid < NBLK*UPB + 4) hs[0][tid] = 0.f;
    if (tid < NBLK*UPB + 4) hs[1][tid] = 0.f;

    int r  = warp;
    int gg = r / UPB, uq = r - gg*UPB;
    int uu_r = u0 + uq;
    int grow = dir*NGT + gg*DHID + uu_r;
    bool rowvalid = (warp < 24) && (uu_r < DHID);
    float xw = 0.f;
    if (rowvalid && lane == 0) {
        int ti0 = dir ? (T-1) : 0;
        xw = __ldg(&xW[(size_t)ti0*XS + grow]);
    }
    float creg = 0.f;
    if (warp == 0 && lane < UPB && u0 + lane < DHID)
        creg = h0[dir*DHID + u0 + lane];
    int pj = ((warp - 24) << 5) + lane;
    int pb = pj >> 1, phalf = pj & 1;
    bool pactive = (warp >= 24) && (pb < NBLK);
    const int4* psrc0 = (const int4*)&g_hline[dir][0][pactive ? pb : 0][phalf*4];
    const int4* psrc1 = (const int4*)&g_hline[dir][1][pactive ? pb : 0][phalf*4];
    __syncthreads();

    for (int t = 0; t < T; ++t) {
        if (warp < 24) {
            const float* hcur = hs[t & 1];
            float s = 0.f;
            #pragma unroll
            for (int i = 0; i < 11; ++i) s += ws[r][lane + 32*i]*hcur[lane + 32*i];
            if (lane < 4) s += ws[r][352 + lane]*hcur[352 + lane];
            #pragma unroll
            for (int o = 16; o; o >>= 1) s += __shfl_down_sync(0xffffffffu, s, o);
            if (lane == 0) zred[r] = s + xw;
            asm volatile("bar.sync 1, 768;" ::: "memory");
            if (warp == 0) {
                float z = (lane < 24) ? zred[lane] : 0.f;
                float a = (lane >= 12 && lane < 18) ? tanhf(z)
                                                    : __fdividef(1.f, 1.f + __expf(-z));
                int u = (lane < UPB) ? lane : 0;
                float si = __shfl_sync(0xffffffffu, a, u);
                float sf = __shfl_sync(0xffffffffu, a, UPB + u);
                float tg = __shfl_sync(0xffffffffu, a, 2*UPB + u);
                float so = __shfl_sync(0xffffffffu, a, 3*UPB + u);
                float h = 0.f;
                int uu = u0 + lane;
                if (lane < UPB && uu < DHID) {
                    creg = sf*creg + si*tg;
                    h = so*tanhf(creg);
                }
                int srcb = 3*(lane & 1);
                float hA = __shfl_sync(0xffffffffu, h, srcb + 0);
                float hB = __shfl_sync(0xffffffffu, h, srcb + 1);
                float hC = __shfl_sync(0xffffffffu, h, srcb + 2);
                if (lane < 2) {
                    int4 v;
                    v.x = t + 1;
                    v.y = __float_as_int(hA);
                    v.z = __float_as_int(hB);
                    v.w = __float_as_int(hC);
                    stv4((int4*)&g_hline[dir][t & 1][blk][lane*4], v);
                }
                int ti = dir ? (T-1-t) : t;
                if (lane < UPB && uu < DHID)
                    out[(size_t)ti*DD2 + dir*DHID + uu] = h;
            }
            if (rowvalid && lane == 0 && t + 1 < T) {
                int tn = dir ? (T-2-t) : (t+1);
                xw = __ldg(&xW[(size_t)tn*XS + grow]);
            }
        } else {
            int tag = t + 1;
            float* hn = hs[(t+1) & 1];
            const int4* src = (t & 1) ? psrc1 : psrc0;
            bool done = !pactive;
            while (__any_sync(0xffffffffu, !done)) {
                if (!done) {
                    int4 v = ldv4(src);
                    if (v.x == tag) {
                        int u = pb*UPB + phalf*3;
                        hn[u]   = __int_as_float(v.y);
                        hn[u+1] = __int_as_float(v.z);
                        hn[u+2] = __int_as_float(v.w);
                        done = true;
                    }
                }
            }
        }
        __syncthreads();
    }
}

// ---------------- row dot (gemv): o[t] = X[t,:K] . w ----------------
__global__ void k_rowdot(const float* __restrict__ X, const float* __restrict__ w,
                         float* __restrict__ o, int T, int K)
{
    int t = blockIdx.x*8 + (threadIdx.x >> 5);
    int lane = threadIdx.x & 31;
    if (t >= T) return;
    float s = 0.f;
    for (int k = lane; k < K; k += 32) s += X[(size_t)t*K + k]*w[k];
    #pragma unroll
    for (int off = 16; off; off >>= 1) s += __shfl_down_sync(0xffffffffu, s, off);
    if (lane == 0) o[t] = s;
}

__global__ void k_scalecols(const float* __restrict__ C, const float* __restrict__ w,
                            float* __restrict__ o, int n)
{
    int i = blockIdx.x*256 + threadIdx.x;
    if (i < n) o[i] = C[i]*w[i % DD2];
}

__global__ void k_qt() {
    int i = blockIdx.x*256 + threadIdx.x;
    if (i < DD2*TQ) { int j = i / TQ, q = i - j*TQ; d_Qt[i] = d_Qb[q*DD2 + j]; }
}

// sim[t][q] += cw[t]+qw[q]; rowmax; row softmax in-place
__global__ void k_simsm() {
    int t = blockIdx.x*8 + (threadIdx.x >> 5);
    int lane = threadIdx.x & 31;
    if (t >= TC) return;
    float cw = d_cw[t];
    float v[4];
    float m = -1e30f;
    #pragma unroll
    for (int i = 0; i < 4; ++i) {
        int q = lane + 32*i;
        v[i] = d_sim[t*TQ + q] + cw + d_qw[q];
        m = fmaxf(m, v[i]);
    }
    #pragma unroll
    for (int off = 16; off; off >>= 1) m = fmaxf(m, __shfl_xor_sync(0xffffffffu, m, off));
    float s = 0.f;
    #pragma unroll
    for (int i = 0; i < 4; ++i) { v[i] = expf(v[i]-m); s += v[i]; }
    #pragma unroll
    for (int off = 16; off; off >>= 1) s += __shfl_xor_sync(0xffffffffu, s, off);
    float inv = 1.f/s;
    #pragma unroll
    for (int i = 0; i < 4; ++i) d_sim[t*TQ + lane + 32*i] = v[i]*inv;
    if (lane == 0) d_rowmax[t] = m;
}

__device__ __forceinline__ float blkMax(float v, float* sh) {
    int lane = threadIdx.x & 31, w = threadIdx.x >> 5;
    #pragma unroll
    for (int o = 16; o; o >>= 1) v = fmaxf(v, __shfl_xor_sync(0xffffffffu, v, o));
    if (lane == 0) sh[w] = v;
    __syncthreads();
    if (w == 0) {
        float x = sh[lane];
        #pragma unroll
        for (int o = 16; o; o >>= 1) x = fmaxf(x, __shfl_xor_sync(0xffffffffu, x, o));
        if (lane == 0) sh[0] = x;
    }
    __syncthreads();
    float r = sh[0];
    __syncthreads();
    return r;
}
__device__ __forceinline__ float blkSum(float v, float* sh) {
    int lane = threadIdx.x & 31, w = threadIdx.x >> 5;
    #pragma unroll
    for (int o = 16; o; o >>= 1) v += __shfl_xor_sync(0xffffffffu, v, o);
    if (lane == 0) sh[w] = v;
    __syncthreads();
    if (w == 0) {
        float x = sh[lane];
        #pragma unroll
        for (int o = 16; o; o >>= 1) x += __shfl_xor_sync(0xffffffffu, x, o);
        if (lane == 0) sh[0] = x;
    }
    __syncthreads();
    float r = sh[0];
    __syncthreads();
    return r;
}

// softmax over rowmax (4096) -> alpha; also zero q2c
__global__ void k_alphasm() {
    __shared__ float sh[32];
    int tid = threadIdx.x;
    float m = -1e30f;
    for (int i = tid; i < TC; i += 1024) m = fmaxf(m, d_rowmax[i]);
    m = blkMax(m, sh);
    float s = 0.f;
    for (int i = tid; i < TC; i += 1024) s += expf(d_rowmax[i] - m);
    s = blkSum(s, sh);
    float inv = 1.f/s;
    for (int i = tid; i < TC; i += 1024) d_alpha[i] = expf(d_rowmax[i] - m)*inv;
    if (tid < DD2) d_q2c[tid] = 0.f;
}

__global__ void k_q2c() {
    int j = blockIdx.x*256 + threadIdx.x;
    int t0 = blockIdx.y*128;
    if (j >= DD2) return;
    float s = 0.f;
    for (int t = t0; t < t0+128; ++t) s += d_alpha[t]*d_Cb[(size_t)t*DD2 + j];
    atomicAdd(&d_q2c[j], s);
}

__global__ void k_qac() {
    int i = blockIdx.x*256 + threadIdx.x;
    if (i >= TC*DD2) return;
    int t = i / DD2, j = i - t*DD2;
    float c = d_Cb[i], a = d_c2q[i];
    float* row = d_qac + (size_t)t*QACD;
    row[j]        = c;
    row[DD2 + j]  = a;
    row[2*DD2 + j]= c*a;
    row[3*DD2 + j]= c*d_q2c[j];
}

// logits[t] = qac[t].w[0:2848] + M[t].w[2848:3560]
__global__ void k_logits(const float* __restrict__ Mx, const float* __restrict__ w) {
    int t = blockIdx.x*8 + (threadIdx.x >> 5);
    int lane = threadIdx.x & 31;
    if (t >= TC) return;
    float s = 0.f;
    const float* qr = d_qac + (size_t)t*QACD;
    for (int k = lane; k < QACD; k += 32) s += qr[k]*w[k];
    const float* mr = Mx + (size_t)t*DD2;
    for (int k = lane; k < DD2; k += 32) s += mr[k]*w[QACD + k];
    #pragma unroll
    for (int off = 16; off; off >>= 1) s += __shfl_down_sync(0xffffffffu, s, off);
    if (lane == 0) d_lg[t] = s;
}

__global__ void k_smout(float* __restrict__ o) {
    __shared__ float sh[32];
    int tid = threadIdx.x;
    float m = -1e30f;
    for (int i = tid; i < TC; i += 1024) m = fmaxf(m, d_lg[i]);
    m = blkMax(m, sh);
    float s = 0.f;
    for (int i = tid; i < TC; i += 1024) s += expf(d_lg[i] - m);
    s = blkSum(s, sh);
    float inv = 1.f/s;
    for (int i = tid; i < TC; i += 1024) o[i] = expf(d_lg[i] - m)*inv;
}

// ---------------- host ----------------
static float* symaddr(const void* sym) {
    void* p = nullptr;
    cudaGetSymbolAddress(&p, sym);
    return (float*)p;
}

static void gemm(const float* A, const float* B, const float* bias, float* C,
                 int M, int N, int K)
{
    dim3 grid((N + 127)/128, (M + 63)/64);
    k_gemm_abt<<<grid, 128>>>(A, B, bias, C, M, N, K);
}

static void scan(const float* xW, const float* Whh,
                 const float* h0, float* out, int T)
{
    k_zerolines<<<1, 1024>>>();
    k_scan<<<2*NBLK, 1024>>>(xW, Whh, h0, out, T);
}

extern "C" void kernel_launch(void* const* d_in, const int* in_sizes, int n_in,
                              void* d_out, int out_size)
{
    const int*   chars_ctx = (const int*)  d_in[0];
    const int*   chars_qry = (const int*)  d_in[1];
    const float* elmo_ctx  = (const float*)d_in[2];
    const float* elmo_qry  = (const float*)d_in[3];
    const float* char_emb  = (const float*)d_in[4];
    const float* conv_w    = (const float*)d_in[5];
    const float* conv_b    = (const float*)d_in[6];
    const float* hw_plain_w= (const float*)d_in[7];
    const float* hw_plain_b= (const float*)d_in[8];
    const float* hw_gate_w = (const float*)d_in[9];
    const float* hw_gate_b = (const float*)d_in[10];
    const float* ctx_Wih   = (const float*)d_in[11];
    const float* ctx_Whh   = (const float*)d_in[12];
    const float* ctx_b     = (const float*)d_in[13];
    const float* sim_w     = (const float*)d_in[14];
    const float* mod1_Wih  = (const float*)d_in[15];
    const float* mod1_Whh  = (const float*)d_in[16];
    const float* mod1_b    = (const float*)d_in[17];
    const float* mod2_Wih  = (const float*)d_in[18];
    const float* mod2_Whh  = (const float*)d_in[19];
    const float* mod2_b    = (const float*)d_in[20];
    const float* pos_Wih   = (const float*)d_in[21];
    const float* pos_Whh   = (const float*)d_in[22];
    const float* pos_b     = (const float*)d_in[23];
    const float* pos1_w    = (const float*)d_in[24];
    const float* pos2_w    = (const float*)d_in[25];
    const float* h0_ctx_c  = (const float*)d_in[26];
    const float* h0_ctx_q  = (const float*)d_in[27];
    const float* h0_mod    = (const float*)d_in[28];
    const float* h0_pos    = (const float*)d_in[29];
    float* out = (float*)d_out;

    float* x_ctx = symaddr(d_x_ctx);
    float* x_qry = symaddr(d_x_qry);
    float* t1    = symaddr(d_t1);
    float* t2    = symaddr(d_t2);
    float* xW    = symaddr(d_xW);
    float* Cb    = symaddr(d_Cb);
    float* Qb    = symaddr(d_Qb);
    float* Qt    = symaddr(d_Qt);
    float* CW    = symaddr(d_CW);
    float* sim   = symaddr(d_sim);
    float* cw    = symaddr(d_cw);
    float* qw    = symaddr(d_qw);
    float* c2q   = symaddr(d_c2q);
    float* qac   = symaddr(d_qac);
    float* Mb    = symaddr(d_Mb);
    float* M2b   = symaddr(d_M2b);

    // 1) char CNN + elmo concat (ordered so launch #5 = a representative GEMM
    //    for the ncu -s 5 -c 1 capture)
    k_convw<<<196, 256>>>(conv_w);                                   // 1
    k_charcnn<<<TC, 128>>>(chars_ctx, char_emb, conv_b, x_ctx);      // 2
    k_elmo<<<(TC*256 + 255)/256, 256>>>(elmo_ctx, x_ctx, TC);        // 3
    k_charcnn<<<TQ, 128>>>(chars_qry, char_emb, conv_b, x_qry);      // 4

    // 2) highway x2 — ctx layer 0 first (gemm is launch #5)
    gemm(x_ctx, hw_gate_w,  hw_gate_b,  t1, TC, DHID, DHID);         // 5 (profiled)
    gemm(x_ctx, hw_plain_w, hw_plain_b, t2, TC, DHID, DHID);
    k_hwy<<<(TC*DHID + 255)/256, 256>>>(x_ctx, t1, t2, TC*DHID);
    k_elmo<<<(TQ*256 + 255)/256, 256>>>(elmo_qry, x_qry, TQ);
    gemm(x_qry, hw_gate_w,  hw_gate_b,  t1, TQ, DHID, DHID);
    gemm(x_qry, hw_plain_w, hw_plain_b, t2, TQ, DHID, DHID);
    k_hwy<<<(TQ*DHID + 255)/256, 256>>>(x_qry, t1, t2, TQ*DHID);
    gemm(x_ctx, hw_gate_w  + DHID*DHID, hw_gate_b  + DHID, t1, TC, DHID, DHID);
    gemm(x_ctx, hw_plain_w + DHID*DHID, hw_plain_b + DHID, t2, TC, DHID, DHID);
    k_hwy<<<(TC*DHID + 255)/256, 256>>>(x_ctx, t1, t2, TC*DHID);
    gemm(x_qry, hw_gate_w  + DHID*DHID, hw_gate_b  + DHID, t1, TQ, DHID, DHID);
    gemm(x_qry, hw_plain_w + DHID*DHID, hw_plain_b + DHID, t2, TQ, DHID, DHID);
    k_hwy<<<(TQ*DHID + 255)/256, 256>>>(x_qry, t1, t2, TQ*DHID);

    // 3) context BiLSTM -> C (combined fwd|bwd N=2848 GEMM)
    gemm(x_ctx, ctx_Wih, ctx_b, xW, TC, 2*NGT, DHID);
    scan(xW, ctx_Whh, h0_ctx_c, Cb, TC);

    // 4) query BiLSTM -> Q
    gemm(x_qry, ctx_Wih, ctx_b, xW, TQ, 2*NGT, DHID);
    scan(xW, ctx_Whh, h0_ctx_q, Qb, TQ);

    // 5) attention
    k_rowdot<<<TC/8, 256>>>(Cb, sim_w,        cw, TC, DD2);
    k_rowdot<<<TQ/8, 256>>>(Qb, sim_w + DD2,  qw, TQ, DD2);
    k_scalecols<<<(TC*DD2 + 255)/256, 256>>>(Cb, sim_w + 2*DD2, CW, TC*DD2);
    gemm(CW, Qb, nullptr, sim, TC, TQ, DD2);      // (C*w_cq) @ Q^T
    k_simsm<<<TC/8, 256>>>();                     // + cw + qw, rowmax, softmax
    k_qt<<<(DD2*TQ + 255)/256, 256>>>();
    gemm(sim, Qt, nullptr, c2q, TC, DD2, TQ);     // attn @ Q
    k_alphasm<<<1, 1024>>>();
    { dim3 gq((DD2 + 255)/256, 32); k_q2c<<<gq, 256>>>(); }
    k_qac<<<(TC*DD2 + 255)/256, 256>>>();

    // 6) mod1 BiLSTM (input 2848) -> M
    gemm(qac, mod1_Wih, mod1_b, xW, TC, 2*NGT, QACD);
    scan(xW, mod1_Whh, h0_mod, Mb, TC);

    // 7) mod2 BiLSTM (input 712) -> M2
    gemm(Mb, mod2_Wih, mod2_b, xW, TC, 2*NGT, DD2);
    scan(xW, mod2_Whh, h0_mod + 2*DHID, M2b, TC);

    // 8) pos1 = softmax([qac, M2] @ pos1_w)
    k_logits<<<TC/8, 256>>>(M2b, pos1_w);
    k_smout<<<1, 1024>>>(out);

    // 9) pos BiLSTM on M2 -> Mb (reuse), pos2
    gemm(M2b, pos_Wih, pos_b, xW, TC, 2*NGT, DD2);
    scan(xW, pos_Whh, h0_pos, Mb, TC);
    k_logits<<<TC/8, 256>>>(Mb, pos2_w);
    k_smout<<<1, 1024>>>(out + TC);
}